// round 12
// baseline (speedup 1.0000x reference)
#include <cuda_runtime.h>
#include <cstdint>

// out = e + (e @ B) @ A^T   with e:[16384,4096] f32, A,B:[4096,16] f32
// Tensor-core path (m16n8k16 bf16, f32 accum) with PERMUTED k and n mappings
// chosen so every per-lane e access is a contiguous float4:
//  - phase 1: k-permutation sigma puts the lane's 4 k-elements at d=4tg..4tg+3
//  - phase 2: paired n-tiles with col = 4*(n>>1) + 2*tile + (n&1) put the
//    lane's 4 output cols at 4tg..4tg+3  -> float4 loads AND stores.
// k0 pre-packs A,B fragments honoring these permutations (gmem, 256KB).
// R12: 16-row blocks (grid 1024) + __launch_bounds__(256,5) for occupancy/tail.

#define MROWS 16384
#define DDIM  4096
#define RANK  16

// Phase-1 B fragments: [kstep(256)][lane(32)] = {ntile0 u64, ntile1 u64}
__device__ __align__(16) ulonglong2 g_Bfrag2[256 * 32];
// Phase-2 A fragments: [ct2(256)][lane(32)] = {t0lo, t0hi, t1lo, t1hi}
__device__ __align__(16) uint4 g_Afrag2[256 * 32];

// pack two f32 -> bf16x2 (lo in low 16 bits)
__device__ __forceinline__ uint32_t pk_bf16(float lo, float hi) {
    uint32_t r;
    asm("cvt.rn.bf16x2.f32 %0, %1, %2;" : "=r"(r) : "f"(hi), "f"(lo));
    return r;
}

// D += A(16x16 bf16, row) * B(16x8 bf16, col), f32 accum (in-place)
__device__ __forceinline__ void mma_bf16(
    float& d0, float& d1, float& d2, float& d3,
    uint32_t a0, uint32_t a1, uint32_t a2, uint32_t a3,
    uint32_t b0, uint32_t b1) {
    asm("mma.sync.aligned.m16n8k16.row.col.f32.bf16.bf16.f32 "
        "{%0,%1,%2,%3},{%4,%5,%6,%7},{%8,%9},{%0,%1,%2,%3};"
        : "+f"(d0), "+f"(d1), "+f"(d2), "+f"(d3)
        : "r"(a0), "r"(a1), "r"(a2), "r"(a3), "r"(b0), "r"(b1));
}

// ---------------- k0: build bf16 fragments for A and B ----------------
// 32768 threads. First 16384: B frags (kstep 256 x nt 2 x 32 lanes).
// Next 16384: A frags (ct2 256 x tile 2 x 32 lanes).
__global__ __launch_bounds__(256) void k0_frags(const float* __restrict__ A,
                                                const float* __restrict__ B) {
    int t = blockIdx.x * 256 + threadIdx.x;
    int lane = t & 31;
    int g = lane >> 2, tg = lane & 3;
    if (t < 16384) {
        int job = t >> 5;
        int kstep = job >> 1, nt = job & 1;
        int k = kstep * 16;
        int c = nt * 8 + g;                 // rank index (n of phase-1 mma)
        // k-permutation sigma: frag k {2tg,2tg+1,2tg+8,2tg+9} -> global
        // d = k + {4tg, 4tg+1, 4tg+2, 4tg+3}
        uint32_t lo = pk_bf16(B[(k + 4 * tg + 0) * RANK + c],
                              B[(k + 4 * tg + 1) * RANK + c]);
        uint32_t hi = pk_bf16(B[(k + 4 * tg + 2) * RANK + c],
                              B[(k + 4 * tg + 3) * RANK + c]);
        reinterpret_cast<unsigned long long*>(g_Bfrag2)
            [(size_t)(kstep * 32 + lane) * 2 + nt] =
            ((unsigned long long)hi << 32) | lo;
    } else {
        int job = (t - 16384) >> 5;
        int ct2 = job >> 1, tile = job & 1;
        // n-permutation over paired tiles: global col for n-index g
        int c = ct2 * 16 + 4 * (g >> 1) + 2 * tile + (g & 1);
        // phase-2 k (rank) mapping is identity
        uint32_t lo = pk_bf16(A[(size_t)c * RANK + 2 * tg],
                              A[(size_t)c * RANK + 2 * tg + 1]);
        uint32_t hi = pk_bf16(A[(size_t)c * RANK + 2 * tg + 8],
                              A[(size_t)c * RANK + 2 * tg + 9]);
        reinterpret_cast<unsigned long long*>(g_Afrag2)
            [(size_t)(ct2 * 32 + lane) * 2 + tile] =
            ((unsigned long long)hi << 32) | lo;
    }
}

// ---------------- fused main kernel ----------------
// grid 1024, block 256 (8 warps). Block owns 16 rows (one m16 tile).
// Phase 1: warp wid does ksteps [wid*32, wid*32+32)  (8-way k-split).
// Phase 2: warp wid does double-tiles [wid*32, wid*32+32).
__global__ __launch_bounds__(256, 5) void fused_mma(const float* __restrict__ e,
                                                    float* __restrict__ out) {
    __shared__ float sacc[8][32][8];    // 8 KB: per-warp partial accum
    __shared__ uint4 stfrag[32];        // 512 B: t as bf16 A-operand frags

    const int tid  = threadIdx.x;
    const int wid  = tid >> 5;
    const int lane = tid & 31;
    const int g    = lane >> 2;   // groupID (row within tile)
    const int tg   = lane & 3;    // thread-in-group
    const int blkrow = blockIdx.x * 16;

    // ======================= Phase 1: t = e @ B =======================
    {
        float tA0 = 0.f, tA1 = 0.f, tA2 = 0.f, tA3 = 0.f;  // ranks 0-7
        float tB0 = 0.f, tB1 = 0.f, tB2 = 0.f, tB3 = 0.f;  // ranks 8-15

        const float* erow = e + (size_t)(blkrow + g) * DDIM + tg * 4;
        const ulonglong2* bf = g_Bfrag2 + (size_t)(wid * 32) * 32 + lane;

#pragma unroll 2
        for (int ks = 0; ks < 32; ks++) {
            const float* ek = erow + (wid * 32 + ks) * 16;
            float4 f0 = *reinterpret_cast<const float4*>(ek);            // row g
            float4 f1 = *reinterpret_cast<const float4*>(ek + 8 * DDIM); // row g+8
            ulonglong2 b = bf[(size_t)ks * 32];

            // sigma mapping: (x,y) -> frag k 2tg,2tg+1 ; (z,w) -> 2tg+8,2tg+9
            uint32_t a0 = pk_bf16(f0.x, f0.y);
            uint32_t a2 = pk_bf16(f0.z, f0.w);
            uint32_t a1 = pk_bf16(f1.x, f1.y);
            uint32_t a3 = pk_bf16(f1.z, f1.w);

            mma_bf16(tA0, tA1, tA2, tA3, a0, a1, a2, a3,
                     (uint32_t)b.x, (uint32_t)(b.x >> 32));
            mma_bf16(tB0, tB1, tB2, tB3, a0, a1, a2, a3,
                     (uint32_t)b.y, (uint32_t)(b.y >> 32));
        }

        float* s = sacc[wid][lane];
        s[0] = tA0; s[1] = tA1; s[2] = tA2; s[3] = tA3;
        s[4] = tB0; s[5] = tB1; s[6] = tB2; s[7] = tB3;
    }
    __syncthreads();

    // reduce 8 k-octants and pack t as bf16 A-operand frags (identity k)
    if (tid < 32) {
        float s[8];
#pragma unroll
        for (int j = 0; j < 8; j++) {
            float v = 0.f;
#pragma unroll
            for (int w = 0; w < 8; w++) v += sacc[w][tid][j];
            s[j] = v;
        }
        stfrag[tid] = make_uint4(pk_bf16(s[0], s[1]), pk_bf16(s[2], s[3]),
                                 pk_bf16(s[4], s[5]), pk_bf16(s[6], s[7]));
    }
    __syncthreads();

    // =================== Phase 2: out = e + t @ A^T ===================
    {
        const uint4 tf = stfrag[lane];

        const float* ebase = e + (size_t)(blkrow + g) * DDIM + tg * 4;
        float* obase = out + (size_t)(blkrow + g) * DDIM + tg * 4;
        const uint4* afp = g_Afrag2 + (size_t)(wid * 32) * 32 + lane;

#pragma unroll 4
        for (int ct = 0; ct < 32; ct++) {
            uint4 af = afp[(size_t)ct * 32];
            const int coff = (wid * 32 + ct) * 16;

            // e rides in the accumulators; lane covers 4 contiguous cols
            float4 e0 = *reinterpret_cast<const float4*>(ebase + coff);
            float4 e1 = *reinterpret_cast<const float4*>(ebase + 8 * DDIM + coff);

            float d0 = e0.x, d1 = e0.y, d2 = e1.x, d3 = e1.y;   // tile0
            float q0 = e0.z, q1 = e0.w, q2 = e1.z, q3 = e1.w;   // tile1

            mma_bf16(d0, d1, d2, d3, tf.x, tf.y, tf.z, tf.w, af.x, af.y);
            mma_bf16(q0, q1, q2, q3, tf.x, tf.y, tf.z, tf.w, af.z, af.w);

            *reinterpret_cast<float4*>(obase + coff) =
                make_float4(d0, d1, q0, q1);
            *reinterpret_cast<float4*>(obase + 8 * DDIM + coff) =
                make_float4(d2, d3, q2, q3);
        }
    }
}

extern "C" void kernel_launch(void* const* d_in, const int* in_sizes, int n_in,
                              void* d_out, int out_size) {
    const float* e = (const float*)d_in[0];  // [4,4096,4096]
    const float* A = (const float*)d_in[1];  // [4096,16]
    const float* B = (const float*)d_in[2];  // [4096,16]
    float* out = (float*)d_out;

    (void)in_sizes; (void)n_in; (void)out_size;

    k0_frags<<<128, 256>>>(A, B);
    fused_mma<<<MROWS / 16, 256>>>(e, out);
}

// round 13
// speedup vs baseline: 1.0836x; 1.0836x over previous
#include <cuda_runtime.h>
#include <cstdint>

// out = e + (e @ B) @ A^T   with e:[16384,4096] f32, A,B:[4096,16] f32
// Tensor-core path (m16n8k16 bf16, f32 accum) with PERMUTED k and n mappings
// chosen so every per-lane e access is a contiguous float4:
//  - phase 1: k-permutation sigma puts the lane's 4 k-elements at d=4tg..4tg+3
//  - phase 2: paired n-tiles with col = 4*(n>>1) + 2*tile + (n&1) put the
//    lane's 4 output cols at 4tg..4tg+3  -> float4 loads AND stores.
// k0 pre-packs A,B fragments honoring these permutations (gmem, 256KB).
// R13: R11 structure (32-row blocks, grid 512) + 2x-batched loads in both
//      phase loops (all loads issued before any consumer) for MLP.

#define MROWS 16384
#define DDIM  4096
#define RANK  16

// Phase-1 B fragments: [kstep(256)][lane(32)] = {ntile0 u64, ntile1 u64}
__device__ __align__(16) ulonglong2 g_Bfrag2[256 * 32];
// Phase-2 A fragments: [ct2(256)][lane(32)] = {t0lo, t0hi, t1lo, t1hi}
__device__ __align__(16) uint4 g_Afrag2[256 * 32];

// pack two f32 -> bf16x2 (lo in low 16 bits)
__device__ __forceinline__ uint32_t pk_bf16(float lo, float hi) {
    uint32_t r;
    asm("cvt.rn.bf16x2.f32 %0, %1, %2;" : "=r"(r) : "f"(hi), "f"(lo));
    return r;
}

// D += A(16x16 bf16, row) * B(16x8 bf16, col), f32 accum (in-place)
__device__ __forceinline__ void mma_bf16(
    float& d0, float& d1, float& d2, float& d3,
    uint32_t a0, uint32_t a1, uint32_t a2, uint32_t a3,
    uint32_t b0, uint32_t b1) {
    asm("mma.sync.aligned.m16n8k16.row.col.f32.bf16.bf16.f32 "
        "{%0,%1,%2,%3},{%4,%5,%6,%7},{%8,%9},{%0,%1,%2,%3};"
        : "+f"(d0), "+f"(d1), "+f"(d2), "+f"(d3)
        : "r"(a0), "r"(a1), "r"(a2), "r"(a3), "r"(b0), "r"(b1));
}

// ---------------- k0: build bf16 fragments for A and B ----------------
__global__ __launch_bounds__(256) void k0_frags(const float* __restrict__ A,
                                                const float* __restrict__ B) {
    int t = blockIdx.x * 256 + threadIdx.x;
    int lane = t & 31;
    int g = lane >> 2, tg = lane & 3;
    if (t < 16384) {
        int job = t >> 5;
        int kstep = job >> 1, nt = job & 1;
        int k = kstep * 16;
        int c = nt * 8 + g;                 // rank index (n of phase-1 mma)
        uint32_t lo = pk_bf16(B[(k + 4 * tg + 0) * RANK + c],
                              B[(k + 4 * tg + 1) * RANK + c]);
        uint32_t hi = pk_bf16(B[(k + 4 * tg + 2) * RANK + c],
                              B[(k + 4 * tg + 3) * RANK + c]);
        reinterpret_cast<unsigned long long*>(g_Bfrag2)
            [(size_t)(kstep * 32 + lane) * 2 + nt] =
            ((unsigned long long)hi << 32) | lo;
    } else {
        int job = (t - 16384) >> 5;
        int ct2 = job >> 1, tile = job & 1;
        int c = ct2 * 16 + 4 * (g >> 1) + 2 * tile + (g & 1);
        uint32_t lo = pk_bf16(A[(size_t)c * RANK + 2 * tg],
                              A[(size_t)c * RANK + 2 * tg + 1]);
        uint32_t hi = pk_bf16(A[(size_t)c * RANK + 2 * tg + 8],
                              A[(size_t)c * RANK + 2 * tg + 9]);
        reinterpret_cast<unsigned long long*>(g_Afrag2)
            [(size_t)(ct2 * 32 + lane) * 2 + tile] =
            ((unsigned long long)hi << 32) | lo;
    }
}

// ---------------- fused main kernel ----------------
// grid 512, block 256 (8 warps). Block owns 32 rows (2 row-tiles of 16).
// Phase 1: warp (rt = wid>>2, q = wid&3) does ksteps [q*64, q*64+64).
// Phase 2: warp (rt = wid&1, cq = wid>>1) does double-tiles [cq*64, +64).
__global__ __launch_bounds__(256, 4) void fused_mma(const float* __restrict__ e,
                                                    float* __restrict__ out) {
    __shared__ float sacc[8][32][8];    // 8 KB: per-warp partial accum
    __shared__ uint4 stfrag[2][32];     // 1 KB: t as bf16 A-operand frags

    const int tid  = threadIdx.x;
    const int wid  = tid >> 5;
    const int lane = tid & 31;
    const int g    = lane >> 2;   // groupID (row within tile)
    const int tg   = lane & 3;    // thread-in-group
    const int blkrow = blockIdx.x * 32;

    // ======================= Phase 1: t = e @ B =======================
    {
        const int rt = wid >> 2;       // row-tile 0/1
        const int q  = wid & 3;        // k quadrant
        const int r0 = blkrow + rt * 16;

        float tA0 = 0.f, tA1 = 0.f, tA2 = 0.f, tA3 = 0.f;  // ranks 0-7
        float tB0 = 0.f, tB1 = 0.f, tB2 = 0.f, tB3 = 0.f;  // ranks 8-15

        const float* erow = e + (size_t)(r0 + g) * DDIM + tg * 4;
        const ulonglong2* bf = g_Bfrag2 + (size_t)(q * 64) * 32 + lane;

#pragma unroll 1
        for (int ks = 0; ks < 64; ks += 2) {
            // ---- batch ALL loads for 2 ksteps first (6 in flight) ----
            const float* ekA = erow + (q * 64 + ks) * 16;
            const float* ekB = ekA + 16;
            float4 fa0 = *reinterpret_cast<const float4*>(ekA);
            float4 fa1 = *reinterpret_cast<const float4*>(ekA + 8 * DDIM);
            float4 fb0 = *reinterpret_cast<const float4*>(ekB);
            float4 fb1 = *reinterpret_cast<const float4*>(ekB + 8 * DDIM);
            ulonglong2 ba = bf[(size_t)ks * 32];
            ulonglong2 bb = bf[(size_t)(ks + 1) * 32];

            // ---- consume kstep ks ----
            uint32_t a0 = pk_bf16(fa0.x, fa0.y);
            uint32_t a2 = pk_bf16(fa0.z, fa0.w);
            uint32_t a1 = pk_bf16(fa1.x, fa1.y);
            uint32_t a3 = pk_bf16(fa1.z, fa1.w);
            mma_bf16(tA0, tA1, tA2, tA3, a0, a1, a2, a3,
                     (uint32_t)ba.x, (uint32_t)(ba.x >> 32));
            mma_bf16(tB0, tB1, tB2, tB3, a0, a1, a2, a3,
                     (uint32_t)ba.y, (uint32_t)(ba.y >> 32));

            // ---- consume kstep ks+1 ----
            uint32_t c0 = pk_bf16(fb0.x, fb0.y);
            uint32_t c2 = pk_bf16(fb0.z, fb0.w);
            uint32_t c1 = pk_bf16(fb1.x, fb1.y);
            uint32_t c3 = pk_bf16(fb1.z, fb1.w);
            mma_bf16(tA0, tA1, tA2, tA3, c0, c1, c2, c3,
                     (uint32_t)bb.x, (uint32_t)(bb.x >> 32));
            mma_bf16(tB0, tB1, tB2, tB3, c0, c1, c2, c3,
                     (uint32_t)bb.y, (uint32_t)(bb.y >> 32));
        }

        float* s = sacc[wid][lane];
        s[0] = tA0; s[1] = tA1; s[2] = tA2; s[3] = tA3;
        s[4] = tB0; s[5] = tB1; s[6] = tB2; s[7] = tB3;
    }
    __syncthreads();

    // reduce 4 k-quadrants and pack t as bf16 A-operand frags (identity k)
    if (tid < 64) {
        const int rt = tid >> 5;
        const int ln = tid & 31;
        float s[8];
#pragma unroll
        for (int j = 0; j < 8; j++)
            s[j] = sacc[rt * 4 + 0][ln][j] + sacc[rt * 4 + 1][ln][j] +
                   sacc[rt * 4 + 2][ln][j] + sacc[rt * 4 + 3][ln][j];
        stfrag[rt][ln] = make_uint4(pk_bf16(s[0], s[1]), pk_bf16(s[2], s[3]),
                                    pk_bf16(s[4], s[5]), pk_bf16(s[6], s[7]));
    }
    __syncthreads();

    // =================== Phase 2: out = e + t @ A^T ===================
    {
        const int rt = wid & 1;
        const int cq = wid >> 1;       // col quarter: 64 double-tiles of 16
        const int r0 = blkrow + rt * 16;

        const uint4 tf = stfrag[rt][lane];

        const float* ebase = e + (size_t)(r0 + g) * DDIM + tg * 4;
        float* obase = out + (size_t)(r0 + g) * DDIM + tg * 4;
        const uint4* afp = g_Afrag2 + (size_t)(cq * 64) * 32 + lane;

#pragma unroll 1
        for (int ct = 0; ct < 64; ct += 2) {
            // ---- batch ALL loads for 2 double-tiles first (6 in flight) ----
            const int ca = (cq * 64 + ct) * 16;
            const int cb = ca + 16;
            uint4 afa = afp[(size_t)ct * 32];
            uint4 afb = afp[(size_t)(ct + 1) * 32];
            float4 ea0 = *reinterpret_cast<const float4*>(ebase + ca);
            float4 ea1 = *reinterpret_cast<const float4*>(ebase + 8 * DDIM + ca);
            float4 eb0 = *reinterpret_cast<const float4*>(ebase + cb);
            float4 eb1 = *reinterpret_cast<const float4*>(ebase + 8 * DDIM + cb);

            // ---- tile-pair a ----
            float d0 = ea0.x, d1 = ea0.y, d2 = ea1.x, d3 = ea1.y;
            float q0 = ea0.z, q1 = ea0.w, q2 = ea1.z, q3 = ea1.w;
            mma_bf16(d0, d1, d2, d3, tf.x, tf.y, tf.z, tf.w, afa.x, afa.y);
            mma_bf16(q0, q1, q2, q3, tf.x, tf.y, tf.z, tf.w, afa.z, afa.w);
            *reinterpret_cast<float4*>(obase + ca) = make_float4(d0, d1, q0, q1);
            *reinterpret_cast<float4*>(obase + 8 * DDIM + ca) =
                make_float4(d2, d3, q2, q3);

            // ---- tile-pair b ----
            float r0f = eb0.x, r1f = eb0.y, r2f = eb1.x, r3f = eb1.y;
            float s0 = eb0.z, s1 = eb0.w, s2 = eb1.z, s3 = eb1.w;
            mma_bf16(r0f, r1f, r2f, r3f, tf.x, tf.y, tf.z, tf.w, afb.x, afb.y);
            mma_bf16(s0, s1, s2, s3, tf.x, tf.y, tf.z, tf.w, afb.z, afb.w);
            *reinterpret_cast<float4*>(obase + cb) =
                make_float4(r0f, r1f, s0, s1);
            *reinterpret_cast<float4*>(obase + 8 * DDIM + cb) =
                make_float4(r2f, r3f, s2, s3);
        }
    }
}

extern "C" void kernel_launch(void* const* d_in, const int* in_sizes, int n_in,
                              void* d_out, int out_size) {
    const float* e = (const float*)d_in[0];  // [4,4096,4096]
    const float* A = (const float*)d_in[1];  // [4096,16]
    const float* B = (const float*)d_in[2];  // [4096,16]
    float* out = (float*)d_out;

    (void)in_sizes; (void)n_in; (void)out_size;

    k0_frags<<<128, 256>>>(A, B);
    fused_mma<<<MROWS / 32, 256>>>(e, out);
}